// round 2
// baseline (speedup 1.0000x reference)
#include <cuda_runtime.h>

#define NN 50000
#define NE 3200000

// ---------------- scratch (static __device__ — no allocations) ----------------
__device__ int g_deg[NN];
__device__ int g_row_start[NN + 1];
__device__ int g_cursor[NN];
__device__ int g_src_sorted[NE];
__device__ int g_eperm[NE];
__device__ __align__(16) float g_edge_part[(size_t)NE * 64];   // 819 MB, sorted-by-dst layout
__device__ __align__(16) float g_np[(size_t)NN * 64];          // node_part = x @ W1_0[0:8]
__device__ __align__(16) float g_aggr[(size_t)NN * 64];
__device__ __align__(16) float g_xA[NN * 8];
__device__ __align__(16) float g_xB[NN * 8];

// ---------------- preprocessing: CSR sort by dst ----------------
__global__ void k_zero_deg() {
    int i = blockIdx.x * blockDim.x + threadIdx.x;
    if (i < NN) g_deg[i] = 0;
}

__global__ void k_hist(const int* __restrict__ ei) {
    int e = blockIdx.x * blockDim.x + threadIdx.x;
    if (e < NE) atomicAdd(&g_deg[ei[NE + e]], 1);
}

__global__ void k_scan() {
    __shared__ int sm[1024];
    __shared__ int carry;
    if (threadIdx.x == 0) carry = 0;
    __syncthreads();
    for (int base = 0; base < NN; base += 1024) {
        int i = base + threadIdx.x;
        int v = (i < NN) ? g_deg[i] : 0;
        sm[threadIdx.x] = v;
        __syncthreads();
        for (int off = 1; off < 1024; off <<= 1) {
            int t = (threadIdx.x >= off) ? sm[threadIdx.x - off] : 0;
            __syncthreads();
            sm[threadIdx.x] += t;
            __syncthreads();
        }
        if (i < NN) {
            int excl = carry + sm[threadIdx.x] - v;
            g_row_start[i] = excl;
            g_cursor[i]    = excl;
        }
        __syncthreads();
        if (threadIdx.x == 0) carry += sm[1023];
        __syncthreads();
    }
    if (threadIdx.x == 0) g_row_start[NN] = NE;
}

__global__ void k_scatter(const int* __restrict__ ei) {
    int e = blockIdx.x * blockDim.x + threadIdx.x;
    if (e < NE) {
        int d = ei[NE + e];
        int pos = atomicAdd(&g_cursor[d], 1);
        g_src_sorted[pos] = ei[e];
        g_eperm[pos] = e;
    }
}

// edge_part[pos][j] = b1_0[j] + sum_k edge_attr[eperm[pos]][k] * w1_0[8+k][j]
// (iteration-invariant; computed once per launch, stored in sorted order)
__global__ void k_edge_part(const float* __restrict__ ea,
                            const float* __restrict__ w1_0,
                            const float* __restrict__ b1_0) {
    __shared__ float Ws[5 * 64];
    __shared__ float Bs[64];
    int tid = threadIdx.x;
    for (int i = tid; i < 320; i += blockDim.x) Ws[i] = w1_0[512 + i];
    if (tid < 64)  Bs[tid] = b1_0[tid];
    __syncthreads();
    long long idx = (long long)blockIdx.x * blockDim.x + tid;
    if (idx >= (long long)NE * 64) return;
    int pos = (int)(idx >> 6);
    int j   = (int)(idx & 63);
    int e   = g_eperm[pos];
    const float* a = ea + (long long)e * 5;
    float s = Bs[j];
    s += a[0] * Ws[0 * 64 + j];
    s += a[1] * Ws[1 * 64 + j];
    s += a[2] * Ws[2 * 64 + j];
    s += a[3] * Ws[3 * 64 + j];
    s += a[4] * Ws[4 * 64 + j];
    g_edge_part[idx] = s;
}

// ---------------- per-iteration kernels ----------------
// node_part[n][j] = sum_{k<8} x[n][k] * w1_0[k][j]
__global__ void k_node_part(const float* __restrict__ x, const float* __restrict__ w1_0) {
    __shared__ float Ws[512];
    int tid = threadIdx.x;
    if (tid < 512) Ws[tid] = w1_0[tid];
    __syncthreads();
    int idx = blockIdx.x * blockDim.x + tid;
    if (idx >= NN * 64) return;
    int n = idx >> 6, j = idx & 63;
    const float* xr = x + n * 8;
    float s = xr[0] * Ws[j]        + xr[1] * Ws[64 + j]
            + xr[2] * Ws[128 + j]  + xr[3] * Ws[192 + j]
            + xr[4] * Ws[256 + j]  + xr[5] * Ws[320 + j]
            + xr[6] * Ws[384 + j]  + xr[7] * Ws[448 + j];
    g_np[idx] = s;
}

// Hot kernel: one warp per dst node. h shared via smem broadcast; W1_1 column
// pair per lane register-resident; 2-edge unroll; fmax-accumulate (init 0 ==
// fused relu + segment_max + empty-segment handling since msg >= 0).
__global__ void __launch_bounds__(128, 3) k_edge(const float* __restrict__ w1_1,
                                                 const float* __restrict__ b1_1) {
    __shared__ __align__(16) float hbuf[4][2][64];
    int lane = threadIdx.x & 31;
    int warp = threadIdx.x >> 5;
    int n = blockIdx.x * 4 + warp;
    if (n >= NN) return;
    int j0 = lane * 2;

    float2 wreg[64];
#pragma unroll
    for (int k = 0; k < 64; k++)
        wreg[k] = *(const float2*)(w1_1 + k * 64 + j0);
    float bx = b1_1[j0], by = b1_1[j0 + 1];

    int beg = g_row_start[n], end = g_row_start[n + 1];
    float accx = 0.f, accy = 0.f;
    float2* hb0 = (float2*)hbuf[warp][0];
    float2* hb1 = (float2*)hbuf[warp][1];
    const float4* h0v = (const float4*)hbuf[warp][0];
    const float4* h1v = (const float4*)hbuf[warp][1];

    for (int i = beg; i < end; i += 2) {
        int s0 = g_src_sorted[i];
        float2 a0 = *(const float2*)(g_np + (size_t)s0 * 64 + j0);
        float2 e0 = *(const float2*)(g_edge_part + (size_t)i * 64 + j0);
        hb0[lane] = make_float2(fmaxf(a0.x + e0.x, 0.f), fmaxf(a0.y + e0.y, 0.f));
        bool has2 = (i + 1 < end);
        if (has2) {
            int s1 = g_src_sorted[i + 1];
            float2 a1 = *(const float2*)(g_np + (size_t)s1 * 64 + j0);
            float2 e1 = *(const float2*)(g_edge_part + (size_t)(i + 1) * 64 + j0);
            hb1[lane] = make_float2(fmaxf(a1.x + e1.x, 0.f), fmaxf(a1.y + e1.y, 0.f));
        }
        __syncwarp();
        float m0x = bx, m0y = by, m1x = bx, m1y = by;
#pragma unroll
        for (int k4 = 0; k4 < 16; k4++) {
            float4 h0 = h0v[k4];
            float4 h1 = h1v[k4];
            float2 w0 = wreg[k4 * 4 + 0];
            m0x += h0.x * w0.x; m0y += h0.x * w0.y; m1x += h1.x * w0.x; m1y += h1.x * w0.y;
            float2 w1 = wreg[k4 * 4 + 1];
            m0x += h0.y * w1.x; m0y += h0.y * w1.y; m1x += h1.y * w1.x; m1y += h1.y * w1.y;
            float2 w2 = wreg[k4 * 4 + 2];
            m0x += h0.z * w2.x; m0y += h0.z * w2.y; m1x += h1.z * w2.x; m1y += h1.z * w2.y;
            float2 w3 = wreg[k4 * 4 + 3];
            m0x += h0.w * w3.x; m0y += h0.w * w3.y; m1x += h1.w * w3.x; m1y += h1.w * w3.y;
        }
        accx = fmaxf(accx, m0x);
        accy = fmaxf(accy, m0y);
        if (has2) { accx = fmaxf(accx, m1x); accy = fmaxf(accy, m1y); }
        __syncwarp();
    }
    *(float2*)(g_aggr + (size_t)n * 64 + j0) = make_float2(accx, accy);
}

// Node-side MLP2 + normalize + output assembly. Thread-per-node, weights smem.
__global__ void __launch_bounds__(128) k_node_update(
    const float* __restrict__ x, float* __restrict__ xout,
    const float* __restrict__ w2_0, const float* __restrict__ b2_0,
    const float* __restrict__ w2_1, const float* __restrict__ b2_1) {
    __shared__ float W0[72 * 32];
    __shared__ float B0[32];
    __shared__ float W1[160];
    __shared__ float B1[8];
    int tid = threadIdx.x;
    for (int i = tid; i < 2304; i += 128) W0[i] = w2_0[i];
    if (tid < 32) B0[tid] = b2_0[tid];
    for (int i = tid; i < 160; i += 128) W1[i] = w2_1[i];
    if (tid < 5) B1[tid] = b2_1[tid];
    __syncthreads();
    int n = blockIdx.x * 128 + tid;
    if (n >= NN) return;

    float cat[72];
#pragma unroll
    for (int k = 0; k < 8; k++) cat[k] = x[n * 8 + k];
    const float4* ag = (const float4*)(g_aggr + (size_t)n * 64);
#pragma unroll
    for (int k = 0; k < 16; k++) {
        float4 v = ag[k];
        cat[8 + 4 * k] = v.x; cat[9 + 4 * k] = v.y;
        cat[10 + 4 * k] = v.z; cat[11 + 4 * k] = v.w;
    }
    float h2[32];
#pragma unroll
    for (int j = 0; j < 32; j++) h2[j] = B0[j];
#pragma unroll 8
    for (int k = 0; k < 72; k++) {
        float c = cat[k];
#pragma unroll
        for (int j = 0; j < 32; j++) h2[j] += c * W0[k * 32 + j];
    }
#pragma unroll
    for (int j = 0; j < 32; j++) h2[j] = fmaxf(h2[j], 0.f);
    float c0 = B1[0], c1 = B1[1], c2 = B1[2], c3 = B1[3], c4 = B1[4];
#pragma unroll
    for (int k = 0; k < 32; k++) {
        float hv = h2[k];
        c0 += hv * W1[k * 5 + 0];
        c1 += hv * W1[k * 5 + 1];
        c2 += hv * W1[k * 5 + 2];
        c3 += hv * W1[k * 5 + 3];
        c4 += hv * W1[k * 5 + 4];
    }
    float nor = sqrtf(c1 * c1 + c2 * c2 + c3 * c3 + c4 * c4);
    float inv = 1.0f / fmaxf(1.0f, nor);
    float* o = xout + n * 8;
    o[0] = c0;
    o[1] = c1 * inv; o[2] = c2 * inv; o[3] = c3 * inv; o[4] = c4 * inv;
    o[5] = cat[0]; o[6] = cat[1]; o[7] = cat[2];
}

// ---------------- launch ----------------
extern "C" void kernel_launch(void* const* d_in, const int* in_sizes, int n_in,
                              void* d_out, int out_size) {
    const float* x         = (const float*)d_in[0];
    const float* edge_attr = (const float*)d_in[1];
    const int*   ei        = (const int*)d_in[2];   // JAX default: int32
    const float* w1_0      = (const float*)d_in[3];
    const float* b1_0      = (const float*)d_in[4];
    const float* w1_1      = (const float*)d_in[5];
    const float* b1_1      = (const float*)d_in[6];
    const float* w2_0      = (const float*)d_in[7];
    const float* b2_0      = (const float*)d_in[8];
    const float* w2_1      = (const float*)d_in[9];
    const float* b2_1      = (const float*)d_in[10];

    // Preprocessing (edge CSR + iteration-invariant edge MLP input part)
    k_zero_deg<<<(NN + 255) / 256, 256>>>();
    k_hist<<<(NE + 255) / 256, 256>>>(ei);
    k_scan<<<1, 1024>>>();
    k_scatter<<<(NE + 255) / 256, 256>>>(ei);
    {
        long long tot = (long long)NE * 64;
        int blocks = (int)((tot + 255) / 256);
        k_edge_part<<<blocks, 256>>>(edge_attr, w1_0, b1_0);
    }

    float *xA = nullptr, *xB = nullptr;
    cudaGetSymbolAddress((void**)&xA, g_xA);
    cudaGetSymbolAddress((void**)&xB, g_xB);

    const float* cur = x;
    for (int it = 0; it < 8; it++) {
        k_node_part<<<(NN * 64 + 511) / 512, 512>>>(cur, w1_0);
        k_edge<<<(NN + 3) / 4, 128>>>(w1_1, b1_1);
        float* nxt = (it == 7) ? (float*)d_out : ((it & 1) ? xB : xA);
        k_node_update<<<(NN + 127) / 128, 128>>>(cur, nxt, w2_0, b2_0, w2_1, b2_1);
        cur = nxt;
    }
}